// round 12
// baseline (speedup 1.0000x reference)
#include <cuda_runtime.h>
#include <cuda_bf16.h>

// Problem constants
#define NPART    148     // persistent CTAs (one per SM)
#define NCHUNK1  4096    // K1: chunks of 64 points  (262144/64);  b = chunk>>10
#define NCHUNK3  2048    // K3: chunks of 128 points (262144/128); b = chunk>>9

// Deterministic scratch (no cudaMalloc allowed)
__device__ float g_part[4 * NPART * 4096];   // per-CTA partial kv  [b][cta][h*1024+d*32+e]
__device__ float g_kv[4 * 4096];             // reduced kv          [b][h*1024+d*32+e]
__device__ float g_wqeff[4 * 16384];         // folded weights      [b][n*128 + c]  (n = e*4+h)

// ---- shared mma.sync infrastructure ----
// bf16 tile [rows][256 bytes], XOR-swizzled at 16B granularity.
__device__ __forceinline__ unsigned sw_off(int row, int kbyte) {
    return (unsigned)((row << 8) + (kbyte ^ ((row & 7) << 4)));
}
// bf16 kn/vn tile [64 rows][512 bytes], XOR-swizzled at 16B granularity.
__device__ __forceinline__ unsigned skvb_off(int row, int chb) {
    return (unsigned)((row << 9) + (chb ^ ((row & 7) << 4)));
}

__device__ __forceinline__ void mma_bf16(float* c,
                                         unsigned a0, unsigned a1, unsigned a2, unsigned a3,
                                         unsigned b0, unsigned b1) {
    asm volatile(
        "mma.sync.aligned.m16n8k16.row.col.f32.bf16.bf16.f32 "
        "{%0,%1,%2,%3}, {%4,%5,%6,%7}, {%8,%9}, {%0,%1,%2,%3};"
        : "+f"(c[0]), "+f"(c[1]), "+f"(c[2]), "+f"(c[3])
        : "r"(a0), "r"(a1), "r"(a2), "r"(a3), "r"(b0), "r"(b1));
}

__device__ __forceinline__ void ldsm4(unsigned* r, unsigned a) {
    asm volatile("ldmatrix.sync.aligned.m8n8.x4.shared.b16 {%0,%1,%2,%3}, [%4];"
                 : "=r"(r[0]), "=r"(r[1]), "=r"(r[2]), "=r"(r[3]) : "r"(a));
}
__device__ __forceinline__ void ldsm4t(unsigned* r, unsigned a) {
    asm volatile("ldmatrix.sync.aligned.m8n8.x4.trans.shared.b16 {%0,%1,%2,%3}, [%4];"
                 : "=r"(r[0]), "=r"(r[1]), "=r"(r[2]), "=r"(r[3]) : "r"(a));
}

// ============================================================================
// Kernel 1 (unchanged from round 11 — best known): 8 proj-MMA warps overlap
// 8 aux warps (tensor-core outer product + X staging).
// ============================================================================
#define K1_WT_HI  0
#define K1_WT_LO  65536
#define K1_XT     131072
#define K1_KVH    163840
#define K1_KVL    196608
#define K1_PARTK  229376
#define K1_PARTV  230400
#define K1_GB     231424
#define K1_SMEM   232448

__global__ void __launch_bounds__(512, 1)
k1_kv_mma(const float* __restrict__ X,
          const float* __restrict__ Wk, const float* __restrict__ Wv,
          const float* __restrict__ gamma, const float* __restrict__ beta)
{
    extern __shared__ char smem[];
    char* wth = smem + K1_WT_HI;
    char* wtl = smem + K1_WT_LO;
    char* xt  = smem + K1_XT;
    char* kvh = smem + K1_KVH;
    char* kvl = smem + K1_KVL;
    float2* partk = (float2*)(smem + K1_PARTK);
    float2* partv = (float2*)(smem + K1_PARTV);
    float2* gb    = (float2*)(smem + K1_GB);

    const unsigned xt_u  = (unsigned)__cvta_generic_to_shared(xt);
    const unsigned wth_u = (unsigned)__cvta_generic_to_shared(wth);
    const unsigned kvh_u = (unsigned)__cvta_generic_to_shared(kvh);

    const int tid  = threadIdx.x;
    const int lane = tid & 31;
    const int warp = tid >> 5;
    const int qr = lane >> 2;
    const int qc = lane & 3;

    for (int idx = tid; idx < 4096; idx += 512) {
        const int c  = idx >> 5;
        const int n4 = (idx & 31) << 2;
        const float4 wk = ((const float4*)Wk)[idx];
        const float4 wv = ((const float4*)Wv)[idx];
#pragma unroll
        for (int j = 0; j < 4; j++) {
            const float vk = (&wk.x)[j];
            const float vv = (&wv.x)[j];
            __nv_bfloat16 hk = __float2bfloat16(vk);
            __nv_bfloat16 hv = __float2bfloat16(vv);
            __nv_bfloat16 lk = __float2bfloat16(vk - __bfloat162float(hk));
            __nv_bfloat16 lv = __float2bfloat16(vv - __bfloat162float(hv));
            const unsigned ok = sw_off(n4 + j,       c * 2);
            const unsigned ov = sw_off(128 + n4 + j, c * 2);
            *(__nv_bfloat16*)(wth + ok) = hk;
            *(__nv_bfloat16*)(wtl + ok) = lk;
            *(__nv_bfloat16*)(wth + ov) = hv;
            *(__nv_bfloat16*)(wtl + ov) = lv;
        }
    }
    if (tid < 128) gb[tid] = make_float2(gamma[tid], beta[tid]);

    const int m0  = (warp & 1) * 32;
    const int n0g = ((warp & 7) >> 1) * 64;
    const int cg  = (warp & 7) >> 1;
    const int kw  = (cg < 2);

    const int laneK = lane & 16;
    const int bKoff = (lane & 8) << 1;
    unsigned aBase[2], aSw[2], bBase[4], bSw[4];
#pragma unroll
    for (int mi = 0; mi < 2; mi++) {
        const int row = m0 + mi * 16 + (lane & 15);
        aSw[mi] = (unsigned)((row & 7) << 4);
        aBase[mi] = xt_u + row * 256;
    }
#pragma unroll
    for (int p = 0; p < 4; p++) {
        const int row = n0g + p * 16 + ((lane >> 1) & 8) + (lane & 7);
        bSw[p] = (unsigned)((row & 7) << 4);
        bBase[p] = wth_u + row * 256;
    }

    const int aw    = warp - 8;
    const int hh2   = (aw >> 1) & 3;
    const int half2 = aw & 1;
    const int rkA = (lane & 7) + ((lane >> 4) & 1) * 8;
    const unsigned chbA = (unsigned)(hh2 * 64 + half2 * 32 + ((lane >> 3) & 1) * 16);
    const unsigned aOut = kvh_u + rkA * 512 + (chbA ^ ((unsigned)(rkA & 7) << 4));
    const int rkB = (lane & 7) + ((lane >> 3) & 1) * 8;
    const unsigned swB = (unsigned)(rkB & 7) << 4;
    const unsigned chbB = (unsigned)(256 + hh2 * 64 + ((lane >> 4) & 1) * 16);
    const unsigned bOut0 = kvh_u + rkB * 512 + (chbB ^ swB);
    const unsigned bOut1 = kvh_u + rkB * 512 + ((chbB + 32) ^ swB);

    float co[4][4];
#pragma unroll
    for (int nt = 0; nt < 4; nt++)
#pragma unroll
        for (int z = 0; z < 4; z++) co[nt][z] = 0.f;

    float4 xr[8];
    const int aux = tid - 256;
    const int chunk0 = blockIdx.x;
    if (warp >= 8) {
        const float4* src = (const float4*)X + (size_t)chunk0 * 2048;
#pragma unroll
        for (int i = 0; i < 8; i++) xr[i] = src[aux + i * 256];
#pragma unroll
        for (int i = 0; i < 8; i++) {
            const int idx = aux + i * 256;
            const int row = idx >> 5;
            const int kb  = (idx & 31) << 3;
            const float4 x = xr[i];
            __nv_bfloat162 h0 = __floats2bfloat162_rn(x.x, x.y);
            __nv_bfloat162 h1 = __floats2bfloat162_rn(x.z, x.w);
            float2 f0 = __bfloat1622float2(h0);
            float2 f1 = __bfloat1622float2(h1);
            __nv_bfloat162 l0 = __floats2bfloat162_rn(x.x - f0.x, x.y - f0.y);
            __nv_bfloat162 l1 = __floats2bfloat162_rn(x.z - f1.x, x.w - f1.y);
            const unsigned off = sw_off(row, kb);
            *(__nv_bfloat162*)(xt + off)             = h0;
            *(__nv_bfloat162*)(xt + off + 4)         = h1;
            *(__nv_bfloat162*)(xt + 16384 + off)     = l0;
            *(__nv_bfloat162*)(xt + 16384 + off + 4) = l1;
        }
        const int c1 = chunk0 + NPART;
        if (c1 < NCHUNK1) {
            const float4* s1 = (const float4*)X + (size_t)c1 * 2048;
#pragma unroll
            for (int i = 0; i < 8; i++) xr[i] = s1[aux + i * 256];
        }
    }
    __syncthreads();

    int pend = -1, ob = -1;
    float c[2][8][4];

    for (int chunk = chunk0; chunk < NCHUNK1; chunk += NPART) {
        if (warp < 8) {
#pragma unroll
            for (int mi = 0; mi < 2; mi++)
#pragma unroll
                for (int nj = 0; nj < 8; nj++)
#pragma unroll
                    for (int z = 0; z < 4; z++) c[mi][nj][z] = 0.f;

#pragma unroll
            for (int ks = 0; ks < 8; ks++) {
                const int kb = ks * 32;
                unsigned ah[2][4], al[2][4];
#pragma unroll
                for (int mi = 0; mi < 2; mi++) {
                    const unsigned off = (unsigned)(kb + laneK) ^ aSw[mi];
                    ldsm4(ah[mi], aBase[mi] + off);
                    ldsm4(al[mi], aBase[mi] + 16384u + off);
                }
#pragma unroll
                for (int p = 0; p < 4; p++) {
                    const unsigned off = (unsigned)(kb + bKoff) ^ bSw[p];
                    unsigned th[4], tl[4];
                    ldsm4(th, bBase[p] + off);
                    ldsm4(tl, bBase[p] + 65536u + off);
#pragma unroll
                    for (int mi = 0; mi < 2; mi++) {
                        float* c0 = c[mi][2 * p];
                        float* c1 = c[mi][2 * p + 1];
                        mma_bf16(c0, ah[mi][0], ah[mi][1], ah[mi][2], ah[mi][3], th[0], th[1]);
                        mma_bf16(c0, ah[mi][0], ah[mi][1], ah[mi][2], ah[mi][3], tl[0], tl[1]);
                        mma_bf16(c0, al[mi][0], al[mi][1], al[mi][2], al[mi][3], th[0], th[1]);
                        mma_bf16(c1, ah[mi][0], ah[mi][1], ah[mi][2], ah[mi][3], th[2], th[3]);
                        mma_bf16(c1, ah[mi][0], ah[mi][1], ah[mi][2], ah[mi][3], tl[2], tl[3]);
                        mma_bf16(c1, al[mi][0], al[mi][1], al[mi][2], al[mi][3], th[2], th[3]);
                    }
                }
            }

#pragma unroll
            for (int mi = 0; mi < 2; mi++) {
#pragma unroll
                for (int half = 0; half < 2; half++) {
                    float s = 0.f, q = 0.f;
#pragma unroll
                    for (int nj = 0; nj < 8; nj++) {
                        const float v0 = c[mi][nj][half * 2];
                        const float v1 = c[mi][nj][half * 2 + 1];
                        s += v0 + v1;
                        q += v0 * v0 + v1 * v1;
                    }
                    s += __shfl_xor_sync(0xffffffffu, s, 1);
                    q += __shfl_xor_sync(0xffffffffu, q, 1);
                    s += __shfl_xor_sync(0xffffffffu, s, 2);
                    q += __shfl_xor_sync(0xffffffffu, q, 2);
                    if (qc == 0) {
                        const int row = m0 + mi * 16 + half * 8 + qr;
                        (kw ? partk : partv)[row * 2 + (cg & 1)] = make_float2(s, q);
                    }
                }
            }
        } else {
            if (pend >= 0) {
                const int bj = pend >> 10;
                if (bj != ob) {
                    if (ob >= 0) {
                        float* dst = g_part + ((size_t)ob * NPART + blockIdx.x) * 4096
                                   + hh2 * 1024 + (half2 * 16 + qr) * 32 + qc * 2;
#pragma unroll
                        for (int nt = 0; nt < 4; nt++) {
                            *(float2*)(dst + nt * 8)           = make_float2(co[nt][0], co[nt][1]);
                            *(float2*)(dst + 8 * 32 + nt * 8)  = make_float2(co[nt][2], co[nt][3]);
#pragma unroll
                            for (int z = 0; z < 4; z++) co[nt][z] = 0.f;
                        }
                    }
                    ob = bj;
                }
#pragma unroll
                for (int ks = 0; ks < 4; ks++) {
                    const unsigned off = (unsigned)(ks * 8192);
                    unsigned Ah[4], Al[4], B0h[4], B1h[4], B0l[4], B1l[4];
                    ldsm4t(Ah, aOut + off);
                    ldsm4t(Al, aOut + 32768u + off);
                    ldsm4t(B0h, bOut0 + off);
                    ldsm4t(B1h, bOut1 + off);
                    ldsm4t(B0l, bOut0 + 32768u + off);
                    ldsm4t(B1l, bOut1 + 32768u + off);
                    mma_bf16(co[0], Ah[0], Ah[1], Ah[2], Ah[3], B0h[0], B0h[1]);
                    mma_bf16(co[0], Ah[0], Ah[1], Ah[2], Ah[3], B0l[0], B0l[1]);
                    mma_bf16(co[0], Al[0], Al[1], Al[2], Al[3], B0h[0], B0h[1]);
                    mma_bf16(co[1], Ah[0], Ah[1], Ah[2], Ah[3], B0h[2], B0h[3]);
                    mma_bf16(co[1], Ah[0], Ah[1], Ah[2], Ah[3], B0l[2], B0l[3]);
                    mma_bf16(co[1], Al[0], Al[1], Al[2], Al[3], B0h[2], B0h[3]);
                    mma_bf16(co[2], Ah[0], Ah[1], Ah[2], Ah[3], B1h[0], B1h[1]);
                    mma_bf16(co[2], Ah[0], Ah[1], Ah[2], Ah[3], B1l[0], B1l[1]);
                    mma_bf16(co[2], Al[0], Al[1], Al[2], Al[3], B1h[0], B1h[1]);
                    mma_bf16(co[3], Ah[0], Ah[1], Ah[2], Ah[3], B1h[2], B1h[3]);
                    mma_bf16(co[3], Ah[0], Ah[1], Ah[2], Ah[3], B1l[2], B1l[3]);
                    mma_bf16(co[3], Al[0], Al[1], Al[2], Al[3], B1h[2], B1h[3]);
                }
            }
        }
        __syncthreads();

        if (warp < 8) {
            const float2* pk = kw ? partk : partv;
#pragma unroll
            for (int mi = 0; mi < 2; mi++) {
#pragma unroll
                for (int half = 0; half < 2; half++) {
                    const int row = m0 + mi * 16 + half * 8 + qr;
                    const float2 p0 = pk[row * 2];
                    const float2 p1 = pk[row * 2 + 1];
                    const float mu = (p0.x + p1.x) * (1.f / 128.f);
                    const float ms = (p0.y + p1.y) * (1.f / 128.f);
                    const float rr = rsqrtf(ms - mu * mu + 1e-5f);
                    const float mm = -mu * rr;
#pragma unroll
                    for (int nj = 0; nj < 8; nj++) {
                        const int ch = (n0g + nj * 8 + qc * 2) & 127;
                        const float2 g0 = gb[ch];
                        const float2 g1 = gb[ch + 1];
                        float& v0 = c[mi][nj][half * 2];
                        float& v1 = c[mi][nj][half * 2 + 1];
                        v0 = fmaf(fmaf(v0, rr, mm), g0.x, g0.y);
                        v1 = fmaf(fmaf(v1, rr, mm), g1.x, g1.y);
                    }
                }
            }
#pragma unroll
            for (int mi = 0; mi < 2; mi++) {
                const int r = m0 + mi * 16 + qr;
#pragma unroll
                for (int nj = 0; nj < 8; nj++) {
                    const int chb = (n0g + nj * 8 + qc * 2) * 2;
                    __nv_bfloat162 h0 = __floats2bfloat162_rn(c[mi][nj][0], c[mi][nj][1]);
                    float2 hf0 = __bfloat1622float2(h0);
                    __nv_bfloat162 l0 = __floats2bfloat162_rn(c[mi][nj][0] - hf0.x,
                                                              c[mi][nj][1] - hf0.y);
                    __nv_bfloat162 h1 = __floats2bfloat162_rn(c[mi][nj][2], c[mi][nj][3]);
                    float2 hf1 = __bfloat1622float2(h1);
                    __nv_bfloat162 l1 = __floats2bfloat162_rn(c[mi][nj][2] - hf1.x,
                                                              c[mi][nj][3] - hf1.y);
                    const unsigned o0 = skvb_off(r,     chb);
                    const unsigned o1 = skvb_off(r + 8, chb);
                    *(__nv_bfloat162*)(kvh + o0) = h0;
                    *(__nv_bfloat162*)(kvl + o0) = l0;
                    *(__nv_bfloat162*)(kvh + o1) = h1;
                    *(__nv_bfloat162*)(kvl + o1) = l1;
                }
            }
        } else {
            const int nxt = chunk + NPART;
            if (nxt < NCHUNK1) {
#pragma unroll
                for (int i = 0; i < 8; i++) {
                    const int idx = aux + i * 256;
                    const int row = idx >> 5;
                    const int kb  = (idx & 31) << 3;
                    const float4 x = xr[i];
                    __nv_bfloat162 h0 = __floats2bfloat162_rn(x.x, x.y);
                    __nv_bfloat162 h1 = __floats2bfloat162_rn(x.z, x.w);
                    float2 f0 = __bfloat1622float2(h0);
                    float2 f1 = __bfloat1622float2(h1);
                    __nv_bfloat162 l0 = __floats2bfloat162_rn(x.x - f0.x, x.y - f0.y);
                    __nv_bfloat162 l1 = __floats2bfloat162_rn(x.z - f1.x, x.w - f1.y);
                    const unsigned off = sw_off(row, kb);
                    *(__nv_bfloat162*)(xt + off)             = h0;
                    *(__nv_bfloat162*)(xt + off + 4)         = h1;
                    *(__nv_bfloat162*)(xt + 16384 + off)     = l0;
                    *(__nv_bfloat162*)(xt + 16384 + off + 4) = l1;
                }
                const int nxt2 = nxt + NPART;
                if (nxt2 < NCHUNK1) {
                    const float4* src = (const float4*)X + (size_t)nxt2 * 2048;
#pragma unroll
                    for (int i = 0; i < 8; i++) xr[i] = src[aux + i * 256];
                }
            }
        }
        pend = chunk;
        __syncthreads();
    }

    if (warp >= 8 && pend >= 0) {
        const int bj = pend >> 10;
        if (bj != ob) {
            if (ob >= 0) {
                float* dst = g_part + ((size_t)ob * NPART + blockIdx.x) * 4096
                           + hh2 * 1024 + (half2 * 16 + qr) * 32 + qc * 2;
#pragma unroll
                for (int nt = 0; nt < 4; nt++) {
                    *(float2*)(dst + nt * 8)          = make_float2(co[nt][0], co[nt][1]);
                    *(float2*)(dst + 8 * 32 + nt * 8) = make_float2(co[nt][2], co[nt][3]);
#pragma unroll
                    for (int z = 0; z < 4; z++) co[nt][z] = 0.f;
                }
            }
            ob = bj;
        }
#pragma unroll
        for (int ks = 0; ks < 4; ks++) {
            const unsigned off = (unsigned)(ks * 8192);
            unsigned Ah[4], Al[4], B0h[4], B1h[4], B0l[4], B1l[4];
            ldsm4t(Ah, aOut + off);
            ldsm4t(Al, aOut + 32768u + off);
            ldsm4t(B0h, bOut0 + off);
            ldsm4t(B1h, bOut1 + off);
            ldsm4t(B0l, bOut0 + 32768u + off);
            ldsm4t(B1l, bOut1 + 32768u + off);
            mma_bf16(co[0], Ah[0], Ah[1], Ah[2], Ah[3], B0h[0], B0h[1]);
            mma_bf16(co[0], Ah[0], Ah[1], Ah[2], Ah[3], B0l[0], B0l[1]);
            mma_bf16(co[0], Al[0], Al[1], Al[2], Al[3], B0h[0], B0h[1]);
            mma_bf16(co[1], Ah[0], Ah[1], Ah[2], Ah[3], B0h[2], B0h[3]);
            mma_bf16(co[1], Ah[0], Ah[1], Ah[2], Ah[3], B0l[2], B0l[3]);
            mma_bf16(co[1], Al[0], Al[1], Al[2], Al[3], B0h[2], B0h[3]);
            mma_bf16(co[2], Ah[0], Ah[1], Ah[2], Ah[3], B1h[0], B1h[1]);
            mma_bf16(co[2], Ah[0], Ah[1], Ah[2], Ah[3], B1l[0], B1l[1]);
            mma_bf16(co[2], Al[0], Al[1], Al[2], Al[3], B1h[0], B1h[1]);
            mma_bf16(co[3], Ah[0], Ah[1], Ah[2], Ah[3], B1h[2], B1h[3]);
            mma_bf16(co[3], Ah[0], Ah[1], Ah[2], Ah[3], B1l[2], B1l[3]);
            mma_bf16(co[3], Al[0], Al[1], Al[2], Al[3], B1h[2], B1h[3]);
        }
        float* dst = g_part + ((size_t)ob * NPART + blockIdx.x) * 4096
                   + hh2 * 1024 + (half2 * 16 + qr) * 32 + qc * 2;
#pragma unroll
        for (int nt = 0; nt < 4; nt++) {
            *(float2*)(dst + nt * 8)          = make_float2(co[nt][0], co[nt][1]);
            *(float2*)(dst + 8 * 32 + nt * 8) = make_float2(co[nt][2], co[nt][3]);
        }
    }
}

// ============================================================================
// Kernel 2a: reduce 148 per-CTA partials -> g_kv.
// ============================================================================
__global__ void k2a_reduce()
{
    const int gid = blockIdx.x * 256 + threadIdx.x;
    const int b = gid >> 12;
    const int e = gid & 4095;
    const float* src = g_part + (size_t)b * NPART * 4096 + e;
    float s = 0.f;
#pragma unroll 4
    for (int j = 0; j < NPART; j++) s += src[(size_t)j * 4096];
    g_kv[gid] = s;
}

// ============================================================================
// Kernel 2b: Wq_eff[b][n][c] = (1/N) * sum_d Wq[c][h*32+d] * kv[b][h][d][e]
// ============================================================================
__global__ void k2b_fold(const float* __restrict__ Wq)
{
    const int gid = blockIdx.x * 256 + threadIdx.x;
    const int b  = gid >> 14;
    const int r  = gid & 16383;
    const int cp = r >> 7;
    const int co = r & 127;
    const int e  = co >> 2;
    const int h  = co & 3;
    const float* wq = Wq + cp * 128 + h * 32;
    const float* kv = g_kv + b * 4096 + h * 1024 + e;
    float s = 0.f;
#pragma unroll
    for (int d = 0; d < 32; d++) s += wq[d] * kv[d * 32];
    g_wqeff[b * 16384 + co * 128 + cp] = s * (1.f / 65536.f);
}

// ============================================================================
// Kernel 3 (warp-specialized): out = X @ Wq_eff[b]^T (bf16x3)
// 8 MMA warps (32x64 tiles) + 8 staging warps (LDG->regs->cvt->XT, double buf).
// smem: Whi 32K | Wlo 32K | XT[2] 2x64K = 192 KB. One bar per chunk.
// ============================================================================
#define K3S_W_HI 0
#define K3S_W_LO 32768
#define K3S_XT   65536     // buf b: hi at +b*65536, lo at +b*65536+32768
#define K3_SMEM  196608

__device__ __forceinline__ void cvt_w512(const float* __restrict__ src,
                                         char* hi_base, char* lo_base, int tid) {
    if (tid < 256) {
#pragma unroll
        for (int i = 0; i < 16; i++) {
            const int idx = tid + i * 256;
            const int row = idx >> 5;
            const int kb  = (idx & 31) << 3;
            const float4 x = *(const float4*)(src + idx * 4);
            __nv_bfloat162 h0 = __floats2bfloat162_rn(x.x, x.y);
            __nv_bfloat162 h1 = __floats2bfloat162_rn(x.z, x.w);
            float2 f0 = __bfloat1622float2(h0);
            float2 f1 = __bfloat1622float2(h1);
            __nv_bfloat162 l0 = __floats2bfloat162_rn(x.x - f0.x, x.y - f0.y);
            __nv_bfloat162 l1 = __floats2bfloat162_rn(x.z - f1.x, x.w - f1.y);
            const unsigned off = sw_off(row, kb);
            *(__nv_bfloat162*)(hi_base + off)     = h0;
            *(__nv_bfloat162*)(hi_base + off + 4) = h1;
            *(__nv_bfloat162*)(lo_base + off)     = l0;
            *(__nv_bfloat162*)(lo_base + off + 4) = l1;
        }
    }
}

// Convert 16 register-resident float4 (one 128x128 tile / 256 threads) into
// hi/lo swizzled bf16 tiles.
__device__ __forceinline__ void cvt_regs256(const float4* xr, char* hi, int sid) {
#pragma unroll
    for (int i = 0; i < 16; i++) {
        const int idx = sid + i * 256;
        const int row = idx >> 5;          // 0..127
        const int kb  = (idx & 31) << 3;
        const float4 x = xr[i];
        __nv_bfloat162 h0 = __floats2bfloat162_rn(x.x, x.y);
        __nv_bfloat162 h1 = __floats2bfloat162_rn(x.z, x.w);
        float2 f0 = __bfloat1622float2(h0);
        float2 f1 = __bfloat1622float2(h1);
        __nv_bfloat162 l0 = __floats2bfloat162_rn(x.x - f0.x, x.y - f0.y);
        __nv_bfloat162 l1 = __floats2bfloat162_rn(x.z - f1.x, x.w - f1.y);
        const unsigned off = sw_off(row, kb);
        *(__nv_bfloat162*)(hi + off)             = h0;
        *(__nv_bfloat162*)(hi + off + 4)         = h1;
        *(__nv_bfloat162*)(hi + 32768 + off)     = l0;
        *(__nv_bfloat162*)(hi + 32768 + off + 4) = l1;
    }
}

__global__ void __launch_bounds__(512, 1)
k3_out_mma(const float* __restrict__ X, float* __restrict__ out)
{
    extern __shared__ char smem[];
    const int tid  = threadIdx.x;
    const int lane = tid & 31;
    const int warp = tid >> 5;   // 0-7 MMA, 8-15 staging

    const unsigned xt_u = (unsigned)__cvta_generic_to_shared(smem + K3S_XT);
    const unsigned wh_u = (unsigned)__cvta_generic_to_shared(smem + K3S_W_HI);

    // MMA warp tile: 32 rows x 64 cols
    const int m0 = (warp & 3) * 32;
    const int n0 = (warp >> 2) * 64;     // 0 or 64 for warps 0-7
    const int qr = lane >> 2;
    const int qc = lane & 3;

    const int laneK = lane & 16;
    const int bKoff = (lane & 8) << 1;
    unsigned aBase[2], aSw[2], bBase[4], bSw[4];
#pragma unroll
    for (int mi = 0; mi < 2; mi++) {
        const int row = m0 + mi * 16 + (lane & 15);
        aSw[mi] = (unsigned)((row & 7) << 4);
        aBase[mi] = xt_u + row * 256;
    }
#pragma unroll
    for (int p = 0; p < 4; p++) {
        const int row = n0 + p * 16 + ((lane >> 1) & 8) + (lane & 7);
        bSw[p] = (unsigned)((row & 7) << 4);
        bBase[p] = wh_u + row * 256;
    }

    // Staging state
    float4 xr[16];
    const int sid = tid & 255;
    const int chunk0 = blockIdx.x;

    // Prolog: staging loads+converts chunk0 into XT[0], prefetches chunk1;
    // MMA warps convert W(b=0).
    if (warp >= 8) {
        const float4* src = (const float4*)X + (size_t)chunk0 * 4096;
#pragma unroll
        for (int i = 0; i < 16; i++) xr[i] = src[sid + i * 256];
        cvt_regs256(xr, smem + K3S_XT, sid);
        const int c1 = chunk0 + NPART;
        if (c1 < NCHUNK3) {
            const float4* s1 = (const float4*)X + (size_t)c1 * 4096;
#pragma unroll
            for (int i = 0; i < 16; i++) xr[i] = s1[sid + i * 256];
        }
    } else {
        cvt_w512(g_wqeff, smem + K3S_W_HI, smem + K3S_W_LO, tid);
    }
    __syncthreads();

    int cur_b = 0;
    int it = 0;
    for (int chunk = chunk0; chunk < NCHUNK3; chunk += NPART, it++) {
        const int cur = it & 1;
        const int b = chunk >> 9;
        if (b != cur_b) {
            // previous iteration's end-bar guarantees no W readers in flight
            cvt_w512(g_wqeff + b * 16384, smem + K3S_W_HI, smem + K3S_W_LO, tid);
            cur_b = b;
            __syncthreads();
        }

        if (warp < 8) {
            // MMA(i) on XT[cur]
            float c[2][8][4];
#pragma unroll
            for (int mi = 0; mi < 2; mi++)
#pragma unroll
                for (int nj = 0; nj < 8; nj++)
#pragma unroll
                    for (int z = 0; z < 4; z++) c[mi][nj][z] = 0.f;

            const unsigned bufo = (unsigned)(cur * 65536);
#pragma unroll
            for (int ks = 0; ks < 8; ks++) {
                const int kb = ks * 32;
                unsigned ah[2][4], al[2][4];
#pragma unroll
                for (int mi = 0; mi < 2; mi++) {
                    const unsigned off = (unsigned)(kb + laneK) ^ aSw[mi];
                    ldsm4(ah[mi], aBase[mi] + bufo + off);
                    ldsm4(al[mi], aBase[mi] + bufo + 32768u + off);
                }
#pragma unroll
                for (int p = 0; p < 4; p++) {
                    const unsigned off = (unsigned)(kb + bKoff) ^ bSw[p];
                    unsigned th[4], tl[4];
                    ldsm4(th, bBase[p] + off);
                    ldsm4(tl, bBase[p] + 32768u + off);
#pragma unroll
                    for (int mi = 0; mi < 2; mi++) {
                        float* c0 = c[mi][2 * p];
                        float* c1 = c[mi][2 * p + 1];
                        mma_bf16(c0, ah[mi][0], ah[mi][1], ah[mi][2], ah[mi][3], th[0], th[1]);
                        mma_bf16(c0, ah[mi][0], ah[mi][1], ah[mi][2], ah[mi][3], tl[0], tl[1]);
                        mma_bf16(c0, al[mi][0], al[mi][1], al[mi][2], al[mi][3], th[0], th[1]);
                        mma_bf16(c1, ah[mi][0], ah[mi][1], ah[mi][2], ah[mi][3], th[2], th[3]);
                        mma_bf16(c1, ah[mi][0], ah[mi][1], ah[mi][2], ah[mi][3], tl[2], tl[3]);
                        mma_bf16(c1, al[mi][0], al[mi][1], al[mi][2], al[mi][3], th[2], th[3]);
                    }
                }
            }

            float* obase = out + (size_t)chunk * 16384;
#pragma unroll
            for (int mi = 0; mi < 2; mi++) {
                const int r = m0 + mi * 16 + qr;
#pragma unroll
                for (int nj = 0; nj < 8; nj++) {
                    const int col = n0 + nj * 8 + qc * 2;
                    *(float2*)(obase + r * 128 + col) =
                        make_float2(c[mi][nj][0], c[mi][nj][1]);
                    *(float2*)(obase + (r + 8) * 128 + col) =
                        make_float2(c[mi][nj][2], c[mi][nj][3]);
                }
            }
        } else {
            // staging: cvt chunk i+1 into XT[cur^1]; LDG chunk i+2 -> regs
            const int nxt = chunk + NPART;
            if (nxt < NCHUNK3) {
                cvt_regs256(xr, smem + K3S_XT + (cur ^ 1) * 65536, sid);
                const int nxt2 = nxt + NPART;
                if (nxt2 < NCHUNK3) {
                    const float4* src = (const float4*)X + (size_t)nxt2 * 4096;
#pragma unroll
                    for (int i = 0; i < 16; i++) xr[i] = src[sid + i * 256];
                }
            }
        }
        __syncthreads();   // XT[cur^1] published; XT[cur] reads done
    }
}

// ============================================================================
extern "C" void kernel_launch(void* const* d_in, const int* in_sizes, int n_in,
                              void* d_out, int out_size)
{
    (void)in_sizes; (void)n_in; (void)out_size;
    const float* X     = (const float*)d_in[0];
    const float* Wq    = (const float*)d_in[1];
    const float* Wk    = (const float*)d_in[2];
    const float* Wv    = (const float*)d_in[3];
    const float* gamma = (const float*)d_in[4];
    const float* beta  = (const float*)d_in[5];
    float* out = (float*)d_out;

    cudaFuncSetAttribute(k1_kv_mma, cudaFuncAttributeMaxDynamicSharedMemorySize,
                         K1_SMEM);    // 227 KB
    cudaFuncSetAttribute(k3_out_mma, cudaFuncAttributeMaxDynamicSharedMemorySize,
                         K3_SMEM);    // 192 KB

    k1_kv_mma<<<NPART, 512, K1_SMEM>>>(X, Wk, Wv, gamma, beta);
    k2a_reduce<<<64, 256>>>();
    k2b_fold<<<256, 256>>>(Wq);
    k3_out_mma<<<NPART, 512, K3_SMEM>>>(X, out);
}

// round 13
// speedup vs baseline: 1.0454x; 1.0454x over previous
#include <cuda_runtime.h>
#include <cuda_bf16.h>

// Problem constants
#define NPART    148     // persistent CTAs (one per SM)
#define NCHUNK1  4096    // K1: chunks of 64 points  (262144/64);  b = chunk>>10
#define NCHUNK3  2048    // K3: chunks of 128 points (262144/128); b = chunk>>9

// Deterministic scratch (no cudaMalloc allowed)
__device__ float g_part[4 * NPART * 4096];   // per-CTA partial kv  [b][cta][h*1024+d*32+e]
__device__ float g_kv[4 * 4096];             // reduced kv          [b][h*1024+d*32+e]
__device__ float g_wqeff[4 * 16384];         // folded weights      [b][n*128 + c]  (n = e*4+h)

// ---- shared mma.sync infrastructure ----
// bf16 tile [rows][256 bytes], XOR-swizzled at 16B granularity.
__device__ __forceinline__ unsigned sw_off(int row, int kbyte) {
    return (unsigned)((row << 8) + (kbyte ^ ((row & 7) << 4)));
}
// bf16 kn/vn tile [64 rows][512 bytes], XOR-swizzled at 16B granularity.
__device__ __forceinline__ unsigned skvb_off(int row, int chb) {
    return (unsigned)((row << 9) + (chb ^ ((row & 7) << 4)));
}

__device__ __forceinline__ void mma_bf16(float* c,
                                         unsigned a0, unsigned a1, unsigned a2, unsigned a3,
                                         unsigned b0, unsigned b1) {
    asm volatile(
        "mma.sync.aligned.m16n8k16.row.col.f32.bf16.bf16.f32 "
        "{%0,%1,%2,%3}, {%4,%5,%6,%7}, {%8,%9}, {%0,%1,%2,%3};"
        : "+f"(c[0]), "+f"(c[1]), "+f"(c[2]), "+f"(c[3])
        : "r"(a0), "r"(a1), "r"(a2), "r"(a3), "r"(b0), "r"(b1));
}

__device__ __forceinline__ void ldsm4(unsigned* r, unsigned a) {
    asm volatile("ldmatrix.sync.aligned.m8n8.x4.shared.b16 {%0,%1,%2,%3}, [%4];"
                 : "=r"(r[0]), "=r"(r[1]), "=r"(r[2]), "=r"(r[3]) : "r"(a));
}
__device__ __forceinline__ void ldsm4t(unsigned* r, unsigned a) {
    asm volatile("ldmatrix.sync.aligned.m8n8.x4.trans.shared.b16 {%0,%1,%2,%3}, [%4];"
                 : "=r"(r[0]), "=r"(r[1]), "=r"(r[2]), "=r"(r[3]) : "r"(a));
}

// ============================================================================
// Kernel 1 (unchanged — round-11 best): 8 proj-MMA warps overlap 8 aux warps
// (tensor-core outer product + X staging). All 16 warps issue tensor ops.
// ============================================================================
#define K1_WT_HI  0
#define K1_WT_LO  65536
#define K1_XT     131072
#define K1_KVH    163840
#define K1_KVL    196608
#define K1_PARTK  229376
#define K1_PARTV  230400
#define K1_GB     231424
#define K1_SMEM   232448

__global__ void __launch_bounds__(512, 1)
k1_kv_mma(const float* __restrict__ X,
          const float* __restrict__ Wk, const float* __restrict__ Wv,
          const float* __restrict__ gamma, const float* __restrict__ beta)
{
    extern __shared__ char smem[];
    char* wth = smem + K1_WT_HI;
    char* wtl = smem + K1_WT_LO;
    char* xt  = smem + K1_XT;
    char* kvh = smem + K1_KVH;
    char* kvl = smem + K1_KVL;
    float2* partk = (float2*)(smem + K1_PARTK);
    float2* partv = (float2*)(smem + K1_PARTV);
    float2* gb    = (float2*)(smem + K1_GB);

    const unsigned xt_u  = (unsigned)__cvta_generic_to_shared(xt);
    const unsigned wth_u = (unsigned)__cvta_generic_to_shared(wth);
    const unsigned kvh_u = (unsigned)__cvta_generic_to_shared(kvh);

    const int tid  = threadIdx.x;
    const int lane = tid & 31;
    const int warp = tid >> 5;
    const int qr = lane >> 2;
    const int qc = lane & 3;

    for (int idx = tid; idx < 4096; idx += 512) {
        const int c  = idx >> 5;
        const int n4 = (idx & 31) << 2;
        const float4 wk = ((const float4*)Wk)[idx];
        const float4 wv = ((const float4*)Wv)[idx];
#pragma unroll
        for (int j = 0; j < 4; j++) {
            const float vk = (&wk.x)[j];
            const float vv = (&wv.x)[j];
            __nv_bfloat16 hk = __float2bfloat16(vk);
            __nv_bfloat16 hv = __float2bfloat16(vv);
            __nv_bfloat16 lk = __float2bfloat16(vk - __bfloat162float(hk));
            __nv_bfloat16 lv = __float2bfloat16(vv - __bfloat162float(hv));
            const unsigned ok = sw_off(n4 + j,       c * 2);
            const unsigned ov = sw_off(128 + n4 + j, c * 2);
            *(__nv_bfloat16*)(wth + ok) = hk;
            *(__nv_bfloat16*)(wtl + ok) = lk;
            *(__nv_bfloat16*)(wth + ov) = hv;
            *(__nv_bfloat16*)(wtl + ov) = lv;
        }
    }
    if (tid < 128) gb[tid] = make_float2(gamma[tid], beta[tid]);

    const int m0  = (warp & 1) * 32;
    const int n0g = ((warp & 7) >> 1) * 64;
    const int cg  = (warp & 7) >> 1;
    const int kw  = (cg < 2);

    const int laneK = lane & 16;
    const int bKoff = (lane & 8) << 1;
    unsigned aBase[2], aSw[2], bBase[4], bSw[4];
#pragma unroll
    for (int mi = 0; mi < 2; mi++) {
        const int row = m0 + mi * 16 + (lane & 15);
        aSw[mi] = (unsigned)((row & 7) << 4);
        aBase[mi] = xt_u + row * 256;
    }
#pragma unroll
    for (int p = 0; p < 4; p++) {
        const int row = n0g + p * 16 + ((lane >> 1) & 8) + (lane & 7);
        bSw[p] = (unsigned)((row & 7) << 4);
        bBase[p] = wth_u + row * 256;
    }

    const int aw    = warp - 8;
    const int hh2   = (aw >> 1) & 3;
    const int half2 = aw & 1;
    const int rkA = (lane & 7) + ((lane >> 4) & 1) * 8;
    const unsigned chbA = (unsigned)(hh2 * 64 + half2 * 32 + ((lane >> 3) & 1) * 16);
    const unsigned aOut = kvh_u + rkA * 512 + (chbA ^ ((unsigned)(rkA & 7) << 4));
    const int rkB = (lane & 7) + ((lane >> 3) & 1) * 8;
    const unsigned swB = (unsigned)(rkB & 7) << 4;
    const unsigned chbB = (unsigned)(256 + hh2 * 64 + ((lane >> 4) & 1) * 16);
    const unsigned bOut0 = kvh_u + rkB * 512 + (chbB ^ swB);
    const unsigned bOut1 = kvh_u + rkB * 512 + ((chbB + 32) ^ swB);

    float co[4][4];
#pragma unroll
    for (int nt = 0; nt < 4; nt++)
#pragma unroll
        for (int z = 0; z < 4; z++) co[nt][z] = 0.f;

    float4 xr[8];
    const int aux = tid - 256;
    const int chunk0 = blockIdx.x;
    if (warp >= 8) {
        const float4* src = (const float4*)X + (size_t)chunk0 * 2048;
#pragma unroll
        for (int i = 0; i < 8; i++) xr[i] = src[aux + i * 256];
#pragma unroll
        for (int i = 0; i < 8; i++) {
            const int idx = aux + i * 256;
            const int row = idx >> 5;
            const int kb  = (idx & 31) << 3;
            const float4 x = xr[i];
            __nv_bfloat162 h0 = __floats2bfloat162_rn(x.x, x.y);
            __nv_bfloat162 h1 = __floats2bfloat162_rn(x.z, x.w);
            float2 f0 = __bfloat1622float2(h0);
            float2 f1 = __bfloat1622float2(h1);
            __nv_bfloat162 l0 = __floats2bfloat162_rn(x.x - f0.x, x.y - f0.y);
            __nv_bfloat162 l1 = __floats2bfloat162_rn(x.z - f1.x, x.w - f1.y);
            const unsigned off = sw_off(row, kb);
            *(__nv_bfloat162*)(xt + off)             = h0;
            *(__nv_bfloat162*)(xt + off + 4)         = h1;
            *(__nv_bfloat162*)(xt + 16384 + off)     = l0;
            *(__nv_bfloat162*)(xt + 16384 + off + 4) = l1;
        }
        const int c1 = chunk0 + NPART;
        if (c1 < NCHUNK1) {
            const float4* s1 = (const float4*)X + (size_t)c1 * 2048;
#pragma unroll
            for (int i = 0; i < 8; i++) xr[i] = s1[aux + i * 256];
        }
    }
    __syncthreads();

    int pend = -1, ob = -1;
    float c[2][8][4];

    for (int chunk = chunk0; chunk < NCHUNK1; chunk += NPART) {
        if (warp < 8) {
#pragma unroll
            for (int mi = 0; mi < 2; mi++)
#pragma unroll
                for (int nj = 0; nj < 8; nj++)
#pragma unroll
                    for (int z = 0; z < 4; z++) c[mi][nj][z] = 0.f;

#pragma unroll
            for (int ks = 0; ks < 8; ks++) {
                const int kb = ks * 32;
                unsigned ah[2][4], al[2][4];
#pragma unroll
                for (int mi = 0; mi < 2; mi++) {
                    const unsigned off = (unsigned)(kb + laneK) ^ aSw[mi];
                    ldsm4(ah[mi], aBase[mi] + off);
                    ldsm4(al[mi], aBase[mi] + 16384u + off);
                }
#pragma unroll
                for (int p = 0; p < 4; p++) {
                    const unsigned off = (unsigned)(kb + bKoff) ^ bSw[p];
                    unsigned th[4], tl[4];
                    ldsm4(th, bBase[p] + off);
                    ldsm4(tl, bBase[p] + 65536u + off);
#pragma unroll
                    for (int mi = 0; mi < 2; mi++) {
                        float* c0 = c[mi][2 * p];
                        float* c1 = c[mi][2 * p + 1];
                        mma_bf16(c0, ah[mi][0], ah[mi][1], ah[mi][2], ah[mi][3], th[0], th[1]);
                        mma_bf16(c0, ah[mi][0], ah[mi][1], ah[mi][2], ah[mi][3], tl[0], tl[1]);
                        mma_bf16(c0, al[mi][0], al[mi][1], al[mi][2], al[mi][3], th[0], th[1]);
                        mma_bf16(c1, ah[mi][0], ah[mi][1], ah[mi][2], ah[mi][3], th[2], th[3]);
                        mma_bf16(c1, ah[mi][0], ah[mi][1], ah[mi][2], ah[mi][3], tl[2], tl[3]);
                        mma_bf16(c1, al[mi][0], al[mi][1], al[mi][2], al[mi][3], th[2], th[3]);
                    }
                }
            }

#pragma unroll
            for (int mi = 0; mi < 2; mi++) {
#pragma unroll
                for (int half = 0; half < 2; half++) {
                    float s = 0.f, q = 0.f;
#pragma unroll
                    for (int nj = 0; nj < 8; nj++) {
                        const float v0 = c[mi][nj][half * 2];
                        const float v1 = c[mi][nj][half * 2 + 1];
                        s += v0 + v1;
                        q += v0 * v0 + v1 * v1;
                    }
                    s += __shfl_xor_sync(0xffffffffu, s, 1);
                    q += __shfl_xor_sync(0xffffffffu, q, 1);
                    s += __shfl_xor_sync(0xffffffffu, s, 2);
                    q += __shfl_xor_sync(0xffffffffu, q, 2);
                    if (qc == 0) {
                        const int row = m0 + mi * 16 + half * 8 + qr;
                        (kw ? partk : partv)[row * 2 + (cg & 1)] = make_float2(s, q);
                    }
                }
            }
        } else {
            if (pend >= 0) {
                const int bj = pend >> 10;
                if (bj != ob) {
                    if (ob >= 0) {
                        float* dst = g_part + ((size_t)ob * NPART + blockIdx.x) * 4096
                                   + hh2 * 1024 + (half2 * 16 + qr) * 32 + qc * 2;
#pragma unroll
                        for (int nt = 0; nt < 4; nt++) {
                            *(float2*)(dst + nt * 8)           = make_float2(co[nt][0], co[nt][1]);
                            *(float2*)(dst + 8 * 32 + nt * 8)  = make_float2(co[nt][2], co[nt][3]);
#pragma unroll
                            for (int z = 0; z < 4; z++) co[nt][z] = 0.f;
                        }
                    }
                    ob = bj;
                }
#pragma unroll
                for (int ks = 0; ks < 4; ks++) {
                    const unsigned off = (unsigned)(ks * 8192);
                    unsigned Ah[4], Al[4], B0h[4], B1h[4], B0l[4], B1l[4];
                    ldsm4t(Ah, aOut + off);
                    ldsm4t(Al, aOut + 32768u + off);
                    ldsm4t(B0h, bOut0 + off);
                    ldsm4t(B1h, bOut1 + off);
                    ldsm4t(B0l, bOut0 + 32768u + off);
                    ldsm4t(B1l, bOut1 + 32768u + off);
                    mma_bf16(co[0], Ah[0], Ah[1], Ah[2], Ah[3], B0h[0], B0h[1]);
                    mma_bf16(co[0], Ah[0], Ah[1], Ah[2], Ah[3], B0l[0], B0l[1]);
                    mma_bf16(co[0], Al[0], Al[1], Al[2], Al[3], B0h[0], B0h[1]);
                    mma_bf16(co[1], Ah[0], Ah[1], Ah[2], Ah[3], B0h[2], B0h[3]);
                    mma_bf16(co[1], Ah[0], Ah[1], Ah[2], Ah[3], B0l[2], B0l[3]);
                    mma_bf16(co[1], Al[0], Al[1], Al[2], Al[3], B0h[2], B0h[3]);
                    mma_bf16(co[2], Ah[0], Ah[1], Ah[2], Ah[3], B1h[0], B1h[1]);
                    mma_bf16(co[2], Ah[0], Ah[1], Ah[2], Ah[3], B1l[0], B1l[1]);
                    mma_bf16(co[2], Al[0], Al[1], Al[2], Al[3], B1h[0], B1h[1]);
                    mma_bf16(co[3], Ah[0], Ah[1], Ah[2], Ah[3], B1h[2], B1h[3]);
                    mma_bf16(co[3], Ah[0], Ah[1], Ah[2], Ah[3], B1l[2], B1l[3]);
                    mma_bf16(co[3], Al[0], Al[1], Al[2], Al[3], B1h[2], B1h[3]);
                }
            }
        }
        __syncthreads();

        if (warp < 8) {
            const float2* pk = kw ? partk : partv;
#pragma unroll
            for (int mi = 0; mi < 2; mi++) {
#pragma unroll
                for (int half = 0; half < 2; half++) {
                    const int row = m0 + mi * 16 + half * 8 + qr;
                    const float2 p0 = pk[row * 2];
                    const float2 p1 = pk[row * 2 + 1];
                    const float mu = (p0.x + p1.x) * (1.f / 128.f);
                    const float ms = (p0.y + p1.y) * (1.f / 128.f);
                    const float rr = rsqrtf(ms - mu * mu + 1e-5f);
                    const float mm = -mu * rr;
#pragma unroll
                    for (int nj = 0; nj < 8; nj++) {
                        const int ch = (n0g + nj * 8 + qc * 2) & 127;
                        const float2 g0 = gb[ch];
                        const float2 g1 = gb[ch + 1];
                        float& v0 = c[mi][nj][half * 2];
                        float& v1 = c[mi][nj][half * 2 + 1];
                        v0 = fmaf(fmaf(v0, rr, mm), g0.x, g0.y);
                        v1 = fmaf(fmaf(v1, rr, mm), g1.x, g1.y);
                    }
                }
            }
#pragma unroll
            for (int mi = 0; mi < 2; mi++) {
                const int r = m0 + mi * 16 + qr;
#pragma unroll
                for (int nj = 0; nj < 8; nj++) {
                    const int chb = (n0g + nj * 8 + qc * 2) * 2;
                    __nv_bfloat162 h0 = __floats2bfloat162_rn(c[mi][nj][0], c[mi][nj][1]);
                    float2 hf0 = __bfloat1622float2(h0);
                    __nv_bfloat162 l0 = __floats2bfloat162_rn(c[mi][nj][0] - hf0.x,
                                                              c[mi][nj][1] - hf0.y);
                    __nv_bfloat162 h1 = __floats2bfloat162_rn(c[mi][nj][2], c[mi][nj][3]);
                    float2 hf1 = __bfloat1622float2(h1);
                    __nv_bfloat162 l1 = __floats2bfloat162_rn(c[mi][nj][2] - hf1.x,
                                                              c[mi][nj][3] - hf1.y);
                    const unsigned o0 = skvb_off(r,     chb);
                    const unsigned o1 = skvb_off(r + 8, chb);
                    *(__nv_bfloat162*)(kvh + o0) = h0;
                    *(__nv_bfloat162*)(kvl + o0) = l0;
                    *(__nv_bfloat162*)(kvh + o1) = h1;
                    *(__nv_bfloat162*)(kvl + o1) = l1;
                }
            }
        } else {
            const int nxt = chunk + NPART;
            if (nxt < NCHUNK1) {
#pragma unroll
                for (int i = 0; i < 8; i++) {
                    const int idx = aux + i * 256;
                    const int row = idx >> 5;
                    const int kb  = (idx & 31) << 3;
                    const float4 x = xr[i];
                    __nv_bfloat162 h0 = __floats2bfloat162_rn(x.x, x.y);
                    __nv_bfloat162 h1 = __floats2bfloat162_rn(x.z, x.w);
                    float2 f0 = __bfloat1622float2(h0);
                    float2 f1 = __bfloat1622float2(h1);
                    __nv_bfloat162 l0 = __floats2bfloat162_rn(x.x - f0.x, x.y - f0.y);
                    __nv_bfloat162 l1 = __floats2bfloat162_rn(x.z - f1.x, x.w - f1.y);
                    const unsigned off = sw_off(row, kb);
                    *(__nv_bfloat162*)(xt + off)             = h0;
                    *(__nv_bfloat162*)(xt + off + 4)         = h1;
                    *(__nv_bfloat162*)(xt + 16384 + off)     = l0;
                    *(__nv_bfloat162*)(xt + 16384 + off + 4) = l1;
                }
                const int nxt2 = nxt + NPART;
                if (nxt2 < NCHUNK1) {
                    const float4* src = (const float4*)X + (size_t)nxt2 * 2048;
#pragma unroll
                    for (int i = 0; i < 8; i++) xr[i] = src[aux + i * 256];
                }
            }
        }
        pend = chunk;
        __syncthreads();
    }

    if (warp >= 8 && pend >= 0) {
        const int bj = pend >> 10;
        if (bj != ob) {
            if (ob >= 0) {
                float* dst = g_part + ((size_t)ob * NPART + blockIdx.x) * 4096
                           + hh2 * 1024 + (half2 * 16 + qr) * 32 + qc * 2;
#pragma unroll
                for (int nt = 0; nt < 4; nt++) {
                    *(float2*)(dst + nt * 8)          = make_float2(co[nt][0], co[nt][1]);
                    *(float2*)(dst + 8 * 32 + nt * 8) = make_float2(co[nt][2], co[nt][3]);
#pragma unroll
                    for (int z = 0; z < 4; z++) co[nt][z] = 0.f;
                }
            }
            ob = bj;
        }
#pragma unroll
        for (int ks = 0; ks < 4; ks++) {
            const unsigned off = (unsigned)(ks * 8192);
            unsigned Ah[4], Al[4], B0h[4], B1h[4], B0l[4], B1l[4];
            ldsm4t(Ah, aOut + off);
            ldsm4t(Al, aOut + 32768u + off);
            ldsm4t(B0h, bOut0 + off);
            ldsm4t(B1h, bOut1 + off);
            ldsm4t(B0l, bOut0 + 32768u + off);
            ldsm4t(B1l, bOut1 + 32768u + off);
            mma_bf16(co[0], Ah[0], Ah[1], Ah[2], Ah[3], B0h[0], B0h[1]);
            mma_bf16(co[0], Ah[0], Ah[1], Ah[2], Ah[3], B0l[0], B0l[1]);
            mma_bf16(co[0], Al[0], Al[1], Al[2], Al[3], B0h[0], B0h[1]);
            mma_bf16(co[1], Ah[0], Ah[1], Ah[2], Ah[3], B0h[2], B0h[3]);
            mma_bf16(co[1], Ah[0], Ah[1], Ah[2], Ah[3], B0l[2], B0l[3]);
            mma_bf16(co[1], Al[0], Al[1], Al[2], Al[3], B0h[2], B0h[3]);
            mma_bf16(co[2], Ah[0], Ah[1], Ah[2], Ah[3], B1h[0], B1h[1]);
            mma_bf16(co[2], Ah[0], Ah[1], Ah[2], Ah[3], B1l[0], B1l[1]);
            mma_bf16(co[2], Al[0], Al[1], Al[2], Al[3], B1h[0], B1h[1]);
            mma_bf16(co[3], Ah[0], Ah[1], Ah[2], Ah[3], B1h[2], B1h[3]);
            mma_bf16(co[3], Ah[0], Ah[1], Ah[2], Ah[3], B1l[2], B1l[3]);
            mma_bf16(co[3], Al[0], Al[1], Al[2], Al[3], B1h[2], B1h[3]);
        }
        float* dst = g_part + ((size_t)ob * NPART + blockIdx.x) * 4096
                   + hh2 * 1024 + (half2 * 16 + qr) * 32 + qc * 2;
#pragma unroll
        for (int nt = 0; nt < 4; nt++) {
            *(float2*)(dst + nt * 8)          = make_float2(co[nt][0], co[nt][1]);
            *(float2*)(dst + 8 * 32 + nt * 8) = make_float2(co[nt][2], co[nt][3]);
        }
    }
}

// ============================================================================
// Kernel 2a: reduce 148 per-CTA partials -> g_kv.
// ============================================================================
__global__ void k2a_reduce()
{
    const int gid = blockIdx.x * 256 + threadIdx.x;
    const int b = gid >> 12;
    const int e = gid & 4095;
    const float* src = g_part + (size_t)b * NPART * 4096 + e;
    float s = 0.f;
#pragma unroll 4
    for (int j = 0; j < NPART; j++) s += src[(size_t)j * 4096];
    g_kv[gid] = s;
}

// ============================================================================
// Kernel 2b: Wq_eff[b][n][c] = (1/N) * sum_d Wq[c][h*32+d] * kv[b][h][d][e]
// ============================================================================
__global__ void k2b_fold(const float* __restrict__ Wq)
{
    const int gid = blockIdx.x * 256 + threadIdx.x;
    const int b  = gid >> 14;
    const int r  = gid & 16383;
    const int cp = r >> 7;
    const int co = r & 127;
    const int e  = co >> 2;
    const int h  = co & 3;
    const float* wq = Wq + cp * 128 + h * 32;
    const float* kv = g_kv + b * 4096 + h * 1024 + e;
    float s = 0.f;
#pragma unroll
    for (int d = 0; d < 32; d++) s += wq[d] * kv[d * 32];
    g_wqeff[b * 16384 + co * 128 + cp] = s * (1.f / 65536.f);
}

// ============================================================================
// Kernel 3: out = X @ Wq_eff[b]^T (bf16x3). ALL 16 warps do MMA (r8 tiles),
// raw staging buffer eliminated: LDG -> regs -> cvt into double-buffered XT.
// smem: Whi 32K | Wlo 32K | XT[2] 2x64K = 192 KB. One bar/chunk.
// ============================================================================
#define K3S_W_HI 0
#define K3S_W_LO 32768
#define K3S_XT   65536     // buf b: hi at +b*65536, lo at +b*65536+32768
#define K3_SMEM  196608

__device__ __forceinline__ void cvt_w512(const float* __restrict__ src,
                                         char* hi_base, char* lo_base, int tid) {
    if (tid < 256) {
#pragma unroll
        for (int i = 0; i < 16; i++) {
            const int idx = tid + i * 256;
            const int row = idx >> 5;
            const int kb  = (idx & 31) << 3;
            const float4 x = *(const float4*)(src + idx * 4);
            __nv_bfloat162 h0 = __floats2bfloat162_rn(x.x, x.y);
            __nv_bfloat162 h1 = __floats2bfloat162_rn(x.z, x.w);
            float2 f0 = __bfloat1622float2(h0);
            float2 f1 = __bfloat1622float2(h1);
            __nv_bfloat162 l0 = __floats2bfloat162_rn(x.x - f0.x, x.y - f0.y);
            __nv_bfloat162 l1 = __floats2bfloat162_rn(x.z - f1.x, x.w - f1.y);
            const unsigned off = sw_off(row, kb);
            *(__nv_bfloat162*)(hi_base + off)     = h0;
            *(__nv_bfloat162*)(hi_base + off + 4) = h1;
            *(__nv_bfloat162*)(lo_base + off)     = l0;
            *(__nv_bfloat162*)(lo_base + off + 4) = l1;
        }
    }
}

// Convert 8 register-resident float4 (128x128 tile / 512 threads) into
// hi/lo swizzled bf16 tiles (lo at hi+32768).
__device__ __forceinline__ void cvt_regs512(const float4* xr, char* hi, int tid) {
#pragma unroll
    for (int i = 0; i < 8; i++) {
        const int idx = tid + i * 512;
        const int row = idx >> 5;          // 0..127
        const int kb  = (idx & 31) << 3;
        const float4 x = xr[i];
        __nv_bfloat162 h0 = __floats2bfloat162_rn(x.x, x.y);
        __nv_bfloat162 h1 = __floats2bfloat162_rn(x.z, x.w);
        float2 f0 = __bfloat1622float2(h0);
        float2 f1 = __bfloat1622float2(h1);
        __nv_bfloat162 l0 = __floats2bfloat162_rn(x.x - f0.x, x.y - f0.y);
        __nv_bfloat162 l1 = __floats2bfloat162_rn(x.z - f1.x, x.w - f1.y);
        const unsigned off = sw_off(row, kb);
        *(__nv_bfloat162*)(hi + off)             = h0;
        *(__nv_bfloat162*)(hi + off + 4)         = h1;
        *(__nv_bfloat162*)(hi + 32768 + off)     = l0;
        *(__nv_bfloat162*)(hi + 32768 + off + 4) = l1;
    }
}

__global__ void __launch_bounds__(512, 1)
k3_out_mma(const float* __restrict__ X, float* __restrict__ out)
{
    extern __shared__ char smem[];
    const int tid  = threadIdx.x;
    const int lane = tid & 31;
    const int warp = tid >> 5;   // all 16 warps do MMA

    const unsigned xt_u = (unsigned)__cvta_generic_to_shared(smem + K3S_XT);
    const unsigned wh_u = (unsigned)__cvta_generic_to_shared(smem + K3S_W_HI);

    const int m0 = (warp & 3) * 32;
    const int n0 = (warp >> 2) * 32;
    const int qr = lane >> 2;
    const int qc = lane & 3;

    const int laneK = lane & 16;
    const int bKoff = (lane & 8) << 1;
    unsigned aBase[2], aSw[2], bBase[2], bSw[2];
#pragma unroll
    for (int mi = 0; mi < 2; mi++) {
        const int row = m0 + mi * 16 + (lane & 15);
        aSw[mi] = (unsigned)((row & 7) << 4);
        aBase[mi] = xt_u + row * 256;
    }
#pragma unroll
    for (int p = 0; p < 2; p++) {
        const int row = n0 + p * 16 + ((lane >> 1) & 8) + (lane & 7);
        bSw[p] = (unsigned)((row & 7) << 4);
        bBase[p] = wh_u + row * 256;
    }

    // Prolog: LDG chunk0 -> regs -> XT[0]; LDG chunk1 -> regs; cvt W(b=0); bar
    float4 xr[8];
    const int chunk0 = blockIdx.x;
    {
        const float4* src = (const float4*)X + (size_t)chunk0 * 4096;
#pragma unroll
        for (int i = 0; i < 8; i++) xr[i] = src[tid + i * 512];
        cvt_regs512(xr, smem + K3S_XT, tid);
        const int c1 = chunk0 + NPART;
        if (c1 < NCHUNK3) {
            const float4* s1 = (const float4*)X + (size_t)c1 * 4096;
#pragma unroll
            for (int i = 0; i < 8; i++) xr[i] = s1[tid + i * 512];
        }
        cvt_w512(g_wqeff, smem + K3S_W_HI, smem + K3S_W_LO, tid);
    }
    __syncthreads();

    int cur_b = 0;
    int it = 0;
    for (int chunk = chunk0; chunk < NCHUNK3; chunk += NPART, it++) {
        const int cur = it & 1;

        // ---- MMA(i) on XT[cur] ----
        float c[2][4][4];
#pragma unroll
        for (int mi = 0; mi < 2; mi++)
#pragma unroll
            for (int nj = 0; nj < 4; nj++)
#pragma unroll
                for (int z = 0; z < 4; z++) c[mi][nj][z] = 0.f;

        const unsigned bufo = (unsigned)(cur * 65536);
#pragma unroll
        for (int ks = 0; ks < 8; ks++) {
            const int kb = ks * 32;
            unsigned ah[2][4], al[2][4], bh[4][2], bl[4][2];
#pragma unroll
            for (int mi = 0; mi < 2; mi++) {
                const unsigned off = (unsigned)(kb + laneK) ^ aSw[mi];
                ldsm4(ah[mi], aBase[mi] + bufo + off);
                ldsm4(al[mi], aBase[mi] + bufo + 32768u + off);
            }
#pragma unroll
            for (int p = 0; p < 2; p++) {
                const unsigned off = (unsigned)(kb + bKoff) ^ bSw[p];
                unsigned t[4];
                ldsm4(t, bBase[p] + off);
                bh[2 * p][0] = t[0]; bh[2 * p][1] = t[1];
                bh[2 * p + 1][0] = t[2]; bh[2 * p + 1][1] = t[3];
                ldsm4(t, bBase[p] + 32768u + off);
                bl[2 * p][0] = t[0]; bl[2 * p][1] = t[1];
                bl[2 * p + 1][0] = t[2]; bl[2 * p + 1][1] = t[3];
            }
#pragma unroll
            for (int mi = 0; mi < 2; mi++)
#pragma unroll
                for (int nj = 0; nj < 4; nj++) {
                    mma_bf16(c[mi][nj], ah[mi][0], ah[mi][1], ah[mi][2], ah[mi][3],
                             bh[nj][0], bh[nj][1]);
                    mma_bf16(c[mi][nj], ah[mi][0], ah[mi][1], ah[mi][2], ah[mi][3],
                             bl[nj][0], bl[nj][1]);
                    mma_bf16(c[mi][nj], al[mi][0], al[mi][1], al[mi][2], al[mi][3],
                             bh[nj][0], bh[nj][1]);
                }
        }

        // ---- store output ----
        float* obase = out + (size_t)chunk * 16384;
#pragma unroll
        for (int mi = 0; mi < 2; mi++) {
            const int r = m0 + mi * 16 + qr;
#pragma unroll
            for (int nj = 0; nj < 4; nj++) {
                const int col = n0 + nj * 8 + qc * 2;
                *(float2*)(obase + r * 128 + col) =
                    make_float2(c[mi][nj][0], c[mi][nj][1]);
                *(float2*)(obase + (r + 8) * 128 + col) =
                    make_float2(c[mi][nj][2], c[mi][nj][3]);
            }
        }

        // ---- stage: cvt regs (chunk i+1) -> XT[cur^1]; LDG chunk i+2 -> regs ----
        const int nxt = chunk + NPART;
        if (nxt < NCHUNK3) {
            cvt_regs512(xr, smem + K3S_XT + (cur ^ 1) * 65536, tid);
            const int nxt2 = nxt + NPART;
            if (nxt2 < NCHUNK3) {
                const float4* src = (const float4*)X + (size_t)nxt2 * 4096;
#pragma unroll
                for (int i = 0; i < 8; i++) xr[i] = src[tid + i * 512];
            }
            // W rewrite for the next chunk's batch (rare): needs all MMA(i) done
            const int bn = nxt >> 9;
            if (bn != cur_b) {
                __syncthreads();
                cvt_w512(g_wqeff + bn * 16384, smem + K3S_W_HI, smem + K3S_W_LO, tid);
                cur_b = bn;
            }
        }
        __syncthreads();   // publishes XT[cur^1] (+W); all XT[cur] reads done
    }
}

// ============================================================================
extern "C" void kernel_launch(void* const* d_in, const int* in_sizes, int n_in,
                              void* d_out, int out_size)
{
    (void)in_sizes; (void)n_in; (void)out_size;
    const float* X     = (const float*)d_in[0];
    const float* Wq    = (const float*)d_in[1];
    const float* Wk    = (const float*)d_in[2];
    const float* Wv    = (const float*)d_in[3];
    const float* gamma = (const float*)d_in[4];
    const float* beta  = (const float*)d_in[5];
    float* out = (float*)d_out;

    cudaFuncSetAttribute(k1_kv_mma, cudaFuncAttributeMaxDynamicSharedMemorySize,
                         K1_SMEM);    // 227 KB
    cudaFuncSetAttribute(k3_out_mma, cudaFuncAttributeMaxDynamicSharedMemorySize,
                         K3_SMEM);    // 192 KB

    k1_kv_mma<<<NPART, 512, K1_SMEM>>>(X, Wk, Wv, gamma, beta);
    k2a_reduce<<<64, 256>>>();
    k2b_fold<<<256, 256>>>(Wq);
    k3_out_mma<<<NPART, 512, K3_SMEM>>>(X, out);
}

// round 14
// speedup vs baseline: 1.1412x; 1.0916x over previous
#include <cuda_runtime.h>
#include <cuda_bf16.h>

// Problem constants
#define NPART    148     // persistent CTAs (one per SM)
#define NCHUNK1  4096    // K1: chunks of 64 points  (262144/64);  b = chunk>>10
#define NCHUNK3  2048    // K3: chunks of 128 points (262144/128); b = chunk>>9

// Deterministic scratch (no cudaMalloc allowed)
__device__ float g_part[4 * NPART * 4096];   // per-CTA partial kv  [b][cta][h*1024+d*32+e]
__device__ float g_kv[4 * 4096];             // reduced kv          [b][h*1024+d*32+e]
__device__ float g_wqeff[4 * 16384];         // folded weights      [b][n*128 + c]  (n = e*4+h)

// ---- cp.async helpers ----
__device__ __forceinline__ void cp16(void* smem_dst, const float* gsrc) {
    unsigned s = (unsigned)__cvta_generic_to_shared(smem_dst);
    asm volatile("cp.async.cg.shared.global [%0], [%1], 16;" :: "r"(s), "l"(gsrc));
}
__device__ __forceinline__ void cp_commit() {
    asm volatile("cp.async.commit_group;");
}
__device__ __forceinline__ void cp_wait_all() {
    asm volatile("cp.async.wait_group 0;");
}

// ---- shared mma.sync infrastructure ----
// bf16 tile [rows][256 bytes], XOR-swizzled at 16B granularity.
__device__ __forceinline__ unsigned sw_off(int row, int kbyte) {
    return (unsigned)((row << 8) + (kbyte ^ ((row & 7) << 4)));
}
// bf16 kn/vn tile [64 rows][512 bytes], XOR-swizzled at 16B granularity.
__device__ __forceinline__ unsigned skvb_off(int row, int chb) {
    return (unsigned)((row << 9) + (chb ^ ((row & 7) << 4)));
}

__device__ __forceinline__ void mma_bf16(float* c,
                                         unsigned a0, unsigned a1, unsigned a2, unsigned a3,
                                         unsigned b0, unsigned b1) {
    asm volatile(
        "mma.sync.aligned.m16n8k16.row.col.f32.bf16.bf16.f32 "
        "{%0,%1,%2,%3}, {%4,%5,%6,%7}, {%8,%9}, {%0,%1,%2,%3};"
        : "+f"(c[0]), "+f"(c[1]), "+f"(c[2]), "+f"(c[3])
        : "r"(a0), "r"(a1), "r"(a2), "r"(a3), "r"(b0), "r"(b1));
}

__device__ __forceinline__ void ldsm4(unsigned* r, unsigned a) {
    asm volatile("ldmatrix.sync.aligned.m8n8.x4.shared.b16 {%0,%1,%2,%3}, [%4];"
                 : "=r"(r[0]), "=r"(r[1]), "=r"(r[2]), "=r"(r[3]) : "r"(a));
}
__device__ __forceinline__ void ldsm4t(unsigned* r, unsigned a) {
    asm volatile("ldmatrix.sync.aligned.m8n8.x4.trans.shared.b16 {%0,%1,%2,%3}, [%4];"
                 : "=r"(r[0]), "=r"(r[1]), "=r"(r[2]), "=r"(r[3]) : "r"(a));
}

// ============================================================================
// Kernel 1 (balanced): ALL 16 warps do proj MMA (16x64 tile, bf16x3) + a
// 16x16 tensor-core outer slice + share LN/store/X-staging.
// smem: WT 128K | XT 32K | KVH 32K | KVL 32K | partk 1K | partv 1K = 226 KB
// ============================================================================
#define K1_WT_HI  0
#define K1_WT_LO  65536
#define K1_XT     131072     // hi at +0 (16K), lo at +16384 (16K)
#define K1_KVH    163840     // [64 pt][256 ch] bf16 hi (32K)
#define K1_KVL    196608     // lo (32K)
#define K1_PARTK  229376     // 64 rows x 2 groups x float2 (1 KB)
#define K1_PARTV  230400     // 1 KB
#define K1_SMEM   231424

__global__ void __launch_bounds__(512, 1)
k1_kv_mma(const float* __restrict__ X,
          const float* __restrict__ Wk, const float* __restrict__ Wv,
          const float* __restrict__ gamma, const float* __restrict__ beta)
{
    extern __shared__ char smem[];
    char* wth = smem + K1_WT_HI;
    char* wtl = smem + K1_WT_LO;
    char* xt  = smem + K1_XT;
    char* kvh = smem + K1_KVH;
    char* kvl = smem + K1_KVL;
    float2* partk = (float2*)(smem + K1_PARTK);
    float2* partv = (float2*)(smem + K1_PARTV);

    const unsigned xt_u  = (unsigned)__cvta_generic_to_shared(xt);
    const unsigned wth_u = (unsigned)__cvta_generic_to_shared(wth);
    const unsigned kvh_u = (unsigned)__cvta_generic_to_shared(kvh);

    const int tid  = threadIdx.x;
    const int lane = tid & 31;
    const int warp = tid >> 5;   // 16 warps, all uniform
    const int qr = lane >> 2;
    const int qc = lane & 3;

    // ---- One-time: transpose + bf16-split Wk|Wv into WT tiles (256 rows) ----
    for (int idx = tid; idx < 4096; idx += 512) {
        const int c  = idx >> 5;
        const int n4 = (idx & 31) << 2;
        const float4 wk = ((const float4*)Wk)[idx];
        const float4 wv = ((const float4*)Wv)[idx];
#pragma unroll
        for (int j = 0; j < 4; j++) {
            const float vk = (&wk.x)[j];
            const float vv = (&wv.x)[j];
            __nv_bfloat16 hk = __float2bfloat16(vk);
            __nv_bfloat16 hv = __float2bfloat16(vv);
            __nv_bfloat16 lk = __float2bfloat16(vk - __bfloat162float(hk));
            __nv_bfloat16 lv = __float2bfloat16(vv - __bfloat162float(hv));
            const unsigned ok = sw_off(n4 + j,       c * 2);
            const unsigned ov = sw_off(128 + n4 + j, c * 2);
            *(__nv_bfloat16*)(wth + ok) = hk;
            *(__nv_bfloat16*)(wtl + ok) = lk;
            *(__nv_bfloat16*)(wth + ov) = hv;
            *(__nv_bfloat16*)(wtl + ov) = lv;
        }
    }

    // ---- proj tile: 16 rows x 64 cols over the 64 x 256 (k|v) output ----
    const int m0  = (warp & 3) * 16;
    const int n0g = (warp >> 2) * 64;      // 0,64,128,192
    const int kw  = (n0g < 128);
    const int cg  = (warp >> 2) & 1;       // group within k or v

    // gamma/beta in registers for this thread's 8 columns
    float gv[8], bv[8];
#pragma unroll
    for (int nj = 0; nj < 8; nj++) {
        const int ch = (n0g + nj * 8 + qc * 2) & 127;
        gv[nj] = gamma[ch];      // col even
        bv[nj] = beta[ch];
    }
    float gv1[8], bv1[8];
#pragma unroll
    for (int nj = 0; nj < 8; nj++) {
        const int ch = (n0g + nj * 8 + qc * 2 + 1) & 127;
        gv1[nj] = gamma[ch];     // col odd
        bv1[nj] = beta[ch];
    }

    const int laneK = lane & 16;
    const int bKoff = (lane & 8) << 1;
    unsigned aBase, aSw, bBase[4], bSw[4];
    {
        const int row = m0 + (lane & 15);
        aSw = (unsigned)((row & 7) << 4);
        aBase = xt_u + row * 256;
    }
#pragma unroll
    for (int p = 0; p < 4; p++) {
        const int row = n0g + p * 16 + ((lane >> 1) & 8) + (lane & 7);
        bSw[p] = (unsigned)((row & 7) << 4);
        bBase[p] = wth_u + row * 256;
    }

    // ---- outer slice: head hh2, d-half dh, e-half eh (16x16 kv tile) ----
    const int hh2 = warp >> 2;
    const int dh  = (warp >> 1) & 1;
    const int eh  = warp & 1;
    const int rkA = (lane & 7) + ((lane >> 4) & 1) * 8;
    const unsigned chbA = (unsigned)(hh2 * 64 + dh * 32 + ((lane >> 3) & 1) * 16);
    const unsigned aOut = kvh_u + rkA * 512 + (chbA ^ ((unsigned)(rkA & 7) << 4));
    const int rkB = (lane & 7) + ((lane >> 3) & 1) * 8;
    const unsigned swB = (unsigned)(rkB & 7) << 4;
    const unsigned chbB = (unsigned)(256 + hh2 * 64 + eh * 32 + ((lane >> 4) & 1) * 16);
    const unsigned bOut = kvh_u + rkB * 512 + (chbB ^ swB);

    float co[2][4];
#pragma unroll
    for (int nt = 0; nt < 2; nt++)
#pragma unroll
        for (int z = 0; z < 4; z++) co[nt][z] = 0.f;

    // ---- X staging: 2048 float4 / 512 threads = 4 per thread ----
    float4 xr[4];
    const int chunk0 = blockIdx.x;
    {
        const float4* src = (const float4*)X + (size_t)chunk0 * 2048;
#pragma unroll
        for (int i = 0; i < 4; i++) xr[i] = src[tid + i * 512];
#pragma unroll
        for (int i = 0; i < 4; i++) {
            const int idx = tid + i * 512;
            const int row = idx >> 5;
            const int kb  = (idx & 31) << 3;
            const float4 x = xr[i];
            __nv_bfloat162 h0 = __floats2bfloat162_rn(x.x, x.y);
            __nv_bfloat162 h1 = __floats2bfloat162_rn(x.z, x.w);
            float2 f0 = __bfloat1622float2(h0);
            float2 f1 = __bfloat1622float2(h1);
            __nv_bfloat162 l0 = __floats2bfloat162_rn(x.x - f0.x, x.y - f0.y);
            __nv_bfloat162 l1 = __floats2bfloat162_rn(x.z - f1.x, x.w - f1.y);
            const unsigned off = sw_off(row, kb);
            *(__nv_bfloat162*)(xt + off)             = h0;
            *(__nv_bfloat162*)(xt + off + 4)         = h1;
            *(__nv_bfloat162*)(xt + 16384 + off)     = l0;
            *(__nv_bfloat162*)(xt + 16384 + off + 4) = l1;
        }
        const int c1 = chunk0 + NPART;
        if (c1 < NCHUNK1) {
            const float4* s1 = (const float4*)X + (size_t)c1 * 2048;
#pragma unroll
            for (int i = 0; i < 4; i++) xr[i] = s1[tid + i * 512];
        }
    }
    __syncthreads();

    int pend = -1, ob = -1;
    float c[8][4];

    for (int chunk = chunk0; chunk < NCHUNK1; chunk += NPART) {
        // ============ PHASE A: outer(i-1) + proj MMA(i) + LN partials ========
        if (pend >= 0) {
            const int bj = pend >> 10;
            if (bj != ob) {
                if (ob >= 0) {
                    float* dst = g_part + ((size_t)ob * NPART + blockIdx.x) * 4096
                               + hh2 * 1024 + (dh * 16 + qr) * 32 + eh * 16 + qc * 2;
#pragma unroll
                    for (int nt = 0; nt < 2; nt++) {
                        *(float2*)(dst + nt * 8)          = make_float2(co[nt][0], co[nt][1]);
                        *(float2*)(dst + 8 * 32 + nt * 8) = make_float2(co[nt][2], co[nt][3]);
#pragma unroll
                        for (int z = 0; z < 4; z++) co[nt][z] = 0.f;
                    }
                }
                ob = bj;
            }
#pragma unroll
            for (int ks = 0; ks < 4; ks++) {
                const unsigned off = (unsigned)(ks * 8192);
                unsigned Ah[4], Al[4], Bh[4], Bl[4];
                ldsm4t(Ah, aOut + off);
                ldsm4t(Al, aOut + 32768u + off);
                ldsm4t(Bh, bOut + off);
                ldsm4t(Bl, bOut + 32768u + off);
                mma_bf16(co[0], Ah[0], Ah[1], Ah[2], Ah[3], Bh[0], Bh[1]);
                mma_bf16(co[0], Ah[0], Ah[1], Ah[2], Ah[3], Bl[0], Bl[1]);
                mma_bf16(co[0], Al[0], Al[1], Al[2], Al[3], Bh[0], Bh[1]);
                mma_bf16(co[1], Ah[0], Ah[1], Ah[2], Ah[3], Bh[2], Bh[3]);
                mma_bf16(co[1], Ah[0], Ah[1], Ah[2], Ah[3], Bl[2], Bl[3]);
                mma_bf16(co[1], Al[0], Al[1], Al[2], Al[3], Bh[2], Bh[3]);
            }
        }

        // ---- proj MMA (bf16x3), 16x64 tile ----
#pragma unroll
        for (int nj = 0; nj < 8; nj++)
#pragma unroll
            for (int z = 0; z < 4; z++) c[nj][z] = 0.f;

#pragma unroll
        for (int ks = 0; ks < 8; ks++) {
            const int kb = ks * 32;
            unsigned ah[4], al[4];
            {
                const unsigned off = (unsigned)(kb + laneK) ^ aSw;
                ldsm4(ah, aBase + off);
                ldsm4(al, aBase + 16384u + off);
            }
#pragma unroll
            for (int p = 0; p < 4; p++) {
                const unsigned off = (unsigned)(kb + bKoff) ^ bSw[p];
                unsigned th[4], tl[4];
                ldsm4(th, bBase[p] + off);
                ldsm4(tl, bBase[p] + 65536u + off);
                float* c0 = c[2 * p];
                float* c1 = c[2 * p + 1];
                mma_bf16(c0, ah[0], ah[1], ah[2], ah[3], th[0], th[1]);
                mma_bf16(c0, ah[0], ah[1], ah[2], ah[3], tl[0], tl[1]);
                mma_bf16(c0, al[0], al[1], al[2], al[3], th[0], th[1]);
                mma_bf16(c1, ah[0], ah[1], ah[2], ah[3], th[2], th[3]);
                mma_bf16(c1, ah[0], ah[1], ah[2], ah[3], tl[2], tl[3]);
                mma_bf16(c1, al[0], al[1], al[2], al[3], th[2], th[3]);
            }
        }

        // ---- LN partial stats over this warp's 64 cols ----
#pragma unroll
        for (int half = 0; half < 2; half++) {
            float s = 0.f, q = 0.f;
#pragma unroll
            for (int nj = 0; nj < 8; nj++) {
                const float v0 = c[nj][half * 2];
                const float v1 = c[nj][half * 2 + 1];
                s += v0 + v1;
                q += v0 * v0 + v1 * v1;
            }
            s += __shfl_xor_sync(0xffffffffu, s, 1);
            q += __shfl_xor_sync(0xffffffffu, q, 1);
            s += __shfl_xor_sync(0xffffffffu, s, 2);
            q += __shfl_xor_sync(0xffffffffu, q, 2);
            if (qc == 0) {
                const int row = m0 + half * 8 + qr;
                (kw ? partk : partv)[row * 2 + cg] = make_float2(s, q);
            }
        }
        __syncthreads();   // bar1: partials visible; outer's kv reads done

        // ============ PHASE B: normalize + store + X staging ================
        {
            const float2* pk = kw ? partk : partv;
#pragma unroll
            for (int half = 0; half < 2; half++) {
                const int row = m0 + half * 8 + qr;
                const float2 p0 = pk[row * 2];
                const float2 p1 = pk[row * 2 + 1];
                const float mu = (p0.x + p1.x) * (1.f / 128.f);
                const float ms = (p0.y + p1.y) * (1.f / 128.f);
                const float rr = rsqrtf(ms - mu * mu + 1e-5f);
                const float mm = -mu * rr;
#pragma unroll
                for (int nj = 0; nj < 8; nj++) {
                    float& v0 = c[nj][half * 2];
                    float& v1 = c[nj][half * 2 + 1];
                    v0 = fmaf(fmaf(v0, rr, mm), gv[nj], bv[nj]);
                    v1 = fmaf(fmaf(v1, rr, mm), gv1[nj], bv1[nj]);
                }
            }
#pragma unroll
            for (int nj = 0; nj < 8; nj++) {
                const int chb = (n0g + nj * 8 + qc * 2) * 2;
                __nv_bfloat162 h0 = __floats2bfloat162_rn(c[nj][0], c[nj][1]);
                float2 hf0 = __bfloat1622float2(h0);
                __nv_bfloat162 l0 = __floats2bfloat162_rn(c[nj][0] - hf0.x,
                                                          c[nj][1] - hf0.y);
                __nv_bfloat162 h1 = __floats2bfloat162_rn(c[nj][2], c[nj][3]);
                float2 hf1 = __bfloat1622float2(h1);
                __nv_bfloat162 l1 = __floats2bfloat162_rn(c[nj][2] - hf1.x,
                                                          c[nj][3] - hf1.y);
                const unsigned o0 = skvb_off(m0 + qr,     chb);
                const unsigned o1 = skvb_off(m0 + 8 + qr, chb);
                *(__nv_bfloat162*)(kvh + o0) = h0;
                *(__nv_bfloat162*)(kvl + o0) = l0;
                *(__nv_bfloat162*)(kvh + o1) = h1;
                *(__nv_bfloat162*)(kvl + o1) = l1;
            }
        }
        // cvt X(i+1) regs -> XT (proj MMA(i) reads finished before bar1)
        {
            const int nxt = chunk + NPART;
            if (nxt < NCHUNK1) {
#pragma unroll
                for (int i = 0; i < 4; i++) {
                    const int idx = tid + i * 512;
                    const int row = idx >> 5;
                    const int kb  = (idx & 31) << 3;
                    const float4 x = xr[i];
                    __nv_bfloat162 h0 = __floats2bfloat162_rn(x.x, x.y);
                    __nv_bfloat162 h1 = __floats2bfloat162_rn(x.z, x.w);
                    float2 f0 = __bfloat1622float2(h0);
                    float2 f1 = __bfloat1622float2(h1);
                    __nv_bfloat162 l0 = __floats2bfloat162_rn(x.x - f0.x, x.y - f0.y);
                    __nv_bfloat162 l1 = __floats2bfloat162_rn(x.z - f1.x, x.w - f1.y);
                    const unsigned off = sw_off(row, kb);
                    *(__nv_bfloat162*)(xt + off)             = h0;
                    *(__nv_bfloat162*)(xt + off + 4)         = h1;
                    *(__nv_bfloat162*)(xt + 16384 + off)     = l0;
                    *(__nv_bfloat162*)(xt + 16384 + off + 4) = l1;
                }
                const int nxt2 = nxt + NPART;
                if (nxt2 < NCHUNK1) {
                    const float4* src = (const float4*)X + (size_t)nxt2 * 2048;
#pragma unroll
                    for (int i = 0; i < 4; i++) xr[i] = src[tid + i * 512];
                }
            }
        }
        pend = chunk;
        __syncthreads();   // bar2: kn/vn(i) + XT(i+1) published
    }

    // Epilogue: outer for the final chunk, then flush
    if (pend >= 0) {
        const int bj = pend >> 10;
        if (bj != ob) {
            if (ob >= 0) {
                float* dst = g_part + ((size_t)ob * NPART + blockIdx.x) * 4096
                           + hh2 * 1024 + (dh * 16 + qr) * 32 + eh * 16 + qc * 2;
#pragma unroll
                for (int nt = 0; nt < 2; nt++) {
                    *(float2*)(dst + nt * 8)          = make_float2(co[nt][0], co[nt][1]);
                    *(float2*)(dst + 8 * 32 + nt * 8) = make_float2(co[nt][2], co[nt][3]);
#pragma unroll
                    for (int z = 0; z < 4; z++) co[nt][z] = 0.f;
                }
            }
            ob = bj;
        }
#pragma unroll
        for (int ks = 0; ks < 4; ks++) {
            const unsigned off = (unsigned)(ks * 8192);
            unsigned Ah[4], Al[4], Bh[4], Bl[4];
            ldsm4t(Ah, aOut + off);
            ldsm4t(Al, aOut + 32768u + off);
            ldsm4t(Bh, bOut + off);
            ldsm4t(Bl, bOut + 32768u + off);
            mma_bf16(co[0], Ah[0], Ah[1], Ah[2], Ah[3], Bh[0], Bh[1]);
            mma_bf16(co[0], Ah[0], Ah[1], Ah[2], Ah[3], Bl[0], Bl[1]);
            mma_bf16(co[0], Al[0], Al[1], Al[2], Al[3], Bh[0], Bh[1]);
            mma_bf16(co[1], Ah[0], Ah[1], Ah[2], Ah[3], Bh[2], Bh[3]);
            mma_bf16(co[1], Ah[0], Ah[1], Ah[2], Ah[3], Bl[2], Bl[3]);
            mma_bf16(co[1], Al[0], Al[1], Al[2], Al[3], Bh[2], Bh[3]);
        }
        float* dst = g_part + ((size_t)ob * NPART + blockIdx.x) * 4096
                   + hh2 * 1024 + (dh * 16 + qr) * 32 + eh * 16 + qc * 2;
#pragma unroll
        for (int nt = 0; nt < 2; nt++) {
            *(float2*)(dst + nt * 8)          = make_float2(co[nt][0], co[nt][1]);
            *(float2*)(dst + 8 * 32 + nt * 8) = make_float2(co[nt][2], co[nt][3]);
        }
    }
}

// ============================================================================
// Kernel 2a: reduce 148 per-CTA partials -> g_kv.
// ============================================================================
__global__ void k2a_reduce()
{
    const int gid = blockIdx.x * 256 + threadIdx.x;
    const int b = gid >> 12;
    const int e = gid & 4095;
    const float* src = g_part + (size_t)b * NPART * 4096 + e;
    float s = 0.f;
#pragma unroll 4
    for (int j = 0; j < NPART; j++) s += src[(size_t)j * 4096];
    g_kv[gid] = s;
}

// ============================================================================
// Kernel 2b: Wq_eff[b][n][c] = (1/N) * sum_d Wq[c][h*32+d] * kv[b][h][d][e]
// ============================================================================
__global__ void k2b_fold(const float* __restrict__ Wq)
{
    const int gid = blockIdx.x * 256 + threadIdx.x;
    const int b  = gid >> 14;
    const int r  = gid & 16383;
    const int cp = r >> 7;
    const int co = r & 127;
    const int e  = co >> 2;
    const int h  = co & 3;
    const float* wq = Wq + cp * 128 + h * 32;
    const float* kv = g_kv + b * 4096 + h * 1024 + e;
    float s = 0.f;
#pragma unroll
    for (int d = 0; d < 32; d++) s += wq[d] * kv[d * 32];
    g_wqeff[b * 16384 + co * 128 + cp] = s * (1.f / 65536.f);
}

// ============================================================================
// Kernel 3 (round-8 version — best known): out = X @ Wq_eff[b]^T (bf16x3)
// 128-pt chunks, cp.async raw staging, ldmatrix fragments.
// smem: Whi 32K | Wlo 32K | Xhi 32K | Xlo 32K | raw 64K = 192 KB
// ============================================================================
#define K3S_W_HI 0
#define K3S_W_LO 32768
#define K3S_X_HI 65536
#define K3S_X_LO 98304
#define K3S_RAW  131072
#define K3_SMEM  196608

__device__ __forceinline__ void cvt_tile512(const float* __restrict__ src,
                                            char* hi_base, char* lo_base, int tid) {
#pragma unroll
    for (int i = 0; i < 8; i++) {
        const int idx = tid + i * 512;
        const int row = idx >> 5;
        const int kb  = (idx & 31) << 3;
        const float4 x = *(const float4*)(src + idx * 4);
        __nv_bfloat162 h0 = __floats2bfloat162_rn(x.x, x.y);
        __nv_bfloat162 h1 = __floats2bfloat162_rn(x.z, x.w);
        float2 f0 = __bfloat1622float2(h0);
        float2 f1 = __bfloat1622float2(h1);
        __nv_bfloat162 l0 = __floats2bfloat162_rn(x.x - f0.x, x.y - f0.y);
        __nv_bfloat162 l1 = __floats2bfloat162_rn(x.z - f1.x, x.w - f1.y);
        const unsigned off = sw_off(row, kb);
        *(__nv_bfloat162*)(hi_base + off)     = h0;
        *(__nv_bfloat162*)(hi_base + off + 4) = h1;
        *(__nv_bfloat162*)(lo_base + off)     = l0;
        *(__nv_bfloat162*)(lo_base + off + 4) = l1;
    }
}

__device__ __forceinline__ void cvt_w512(const float* __restrict__ src,
                                         char* hi_base, char* lo_base, int tid) {
    if (tid < 256) {
#pragma unroll
        for (int i = 0; i < 16; i++) {
            const int idx = tid + i * 256;
            const int row = idx >> 5;
            const int kb  = (idx & 31) << 3;
            const float4 x = *(const float4*)(src + idx * 4);
            __nv_bfloat162 h0 = __floats2bfloat162_rn(x.x, x.y);
            __nv_bfloat162 h1 = __floats2bfloat162_rn(x.z, x.w);
            float2 f0 = __bfloat1622float2(h0);
            float2 f1 = __bfloat1622float2(h1);
            __nv_bfloat162 l0 = __floats2bfloat162_rn(x.x - f0.x, x.y - f0.y);
            __nv_bfloat162 l1 = __floats2bfloat162_rn(x.z - f1.x, x.w - f1.y);
            const unsigned off = sw_off(row, kb);
            *(__nv_bfloat162*)(hi_base + off)     = h0;
            *(__nv_bfloat162*)(hi_base + off + 4) = h1;
            *(__nv_bfloat162*)(lo_base + off)     = l0;
            *(__nv_bfloat162*)(lo_base + off + 4) = l1;
        }
    }
}

__global__ void __launch_bounds__(512, 1)
k3_out_mma(const float* __restrict__ X, float* __restrict__ out)
{
    extern __shared__ char smem[];
    const int tid  = threadIdx.x;
    const int lane = tid & 31;
    const int warp = tid >> 5;

    const int m0 = (warp & 3) * 32;
    const int n0 = (warp >> 2) * 32;
    const int qr = lane >> 2;
    const int qc = lane & 3;

    float* raw = (float*)(smem + K3S_RAW);

    const unsigned xh_u = (unsigned)__cvta_generic_to_shared(smem + K3S_X_HI);
    const unsigned wh_u = (unsigned)__cvta_generic_to_shared(smem + K3S_W_HI);

    const int laneK = lane & 16;
    const int bKoff = (lane & 8) << 1;
    unsigned aBase[2], aSw[2], bBase[2], bSw[2];
#pragma unroll
    for (int mi = 0; mi < 2; mi++) {
        const int row = m0 + mi * 16 + (lane & 15);
        aSw[mi] = (unsigned)((row & 7) << 4);
        aBase[mi] = xh_u + row * 256;
    }
#pragma unroll
    for (int p = 0; p < 2; p++) {
        const int row = n0 + p * 16 + ((lane >> 1) & 8) + (lane & 7);
        bSw[p] = (unsigned)((row & 7) << 4);
        bBase[p] = wh_u + row * 256;
    }

    {
        const float* src = X + (size_t)blockIdx.x * 16384;
#pragma unroll
        for (int i = 0; i < 8; i++)
            cp16(raw + (tid + i * 512) * 4, src + (tid + i * 512) * 4);
        cp_commit();
    }

    int cur_b = -1;
    for (int chunk = blockIdx.x; chunk < NCHUNK3; chunk += NPART) {
        const int b = chunk >> 9;

        cp_wait_all();
        __syncthreads();

        if (b != cur_b) {
            cvt_w512(g_wqeff + b * 16384, smem + K3S_W_HI, smem + K3S_W_LO, tid);
            cur_b = b;
        }
        cvt_tile512(raw, smem + K3S_X_HI, smem + K3S_X_LO, tid);
        __syncthreads();

        {
            const int nxt = chunk + NPART;
            if (nxt < NCHUNK3) {
                const float* src = X + (size_t)nxt * 16384;
#pragma unroll
                for (int i = 0; i < 8; i++)
                    cp16(raw + (tid + i * 512) * 4, src + (tid + i * 512) * 4);
                cp_commit();
            }
        }

        float c[2][4][4];
#pragma unroll
        for (int mi = 0; mi < 2; mi++)
#pragma unroll
            for (int nj = 0; nj < 4; nj++)
#pragma unroll
                for (int z = 0; z < 4; z++) c[mi][nj][z] = 0.f;

#pragma unroll
        for (int ks = 0; ks < 8; ks++) {
            const int kb = ks * 32;
            unsigned ah[2][4], al[2][4], bh[4][2], bl[4][2];
#pragma unroll
            for (int mi = 0; mi < 2; mi++) {
                const unsigned off = (unsigned)(kb + laneK) ^ aSw[mi];
                ldsm4(ah[mi], aBase[mi] + off);
                ldsm4(al[mi], aBase[mi] + 32768u + off);
            }
#pragma unroll
            for (int p = 0; p < 2; p++) {
                const unsigned off = (unsigned)(kb + bKoff) ^ bSw[p];
                unsigned t[4];
                ldsm4(t, bBase[p] + off);
                bh[2 * p][0] = t[0]; bh[2 * p][1] = t[1];
                bh[2 * p + 1][0] = t[2]; bh[2 * p + 1][1] = t[3];
                ldsm4(t, bBase[p] + 32768u + off);
                bl[2 * p][0] = t[0]; bl[2 * p][1] = t[1];
                bl[2 * p + 1][0] = t[2]; bl[2 * p + 1][1] = t[3];
            }
#pragma unroll
            for (int mi = 0; mi < 2; mi++)
#pragma unroll
                for (int nj = 0; nj < 4; nj++) {
                    mma_bf16(c[mi][nj], ah[mi][0], ah[mi][1], ah[mi][2], ah[mi][3],
                             bh[nj][0], bh[nj][1]);
                    mma_bf16(c[mi][nj], ah[mi][0], ah[mi][1], ah[mi][2], ah[mi][3],
                             bl[nj][0], bl[nj][1]);
                    mma_bf16(c[mi][nj], al[mi][0], al[mi][1], al[mi][2], al[mi][3],
                             bh[nj][0], bh[nj][1]);
                }
        }

        float* obase = out + (size_t)chunk * 16384;
#pragma unroll
        for (int mi = 0; mi < 2; mi++) {
            const int r = m0 + mi * 16 + qr;
#pragma unroll
            for (int nj = 0; nj < 4; nj++) {
                const int col = n0 + nj * 8 + qc * 2;
                *(float2*)(obase + r * 128 + col) =
                    make_float2(c[mi][nj][0], c[mi][nj][1]);
                *(float2*)(obase + (r + 8) * 128 + col) =
                    make_float2(c[mi][nj][2], c[mi][nj][3]);
            }
        }
    }
}

// ============================================================================
extern "C" void kernel_launch(void* const* d_in, const int* in_sizes, int n_in,
                              void* d_out, int out_size)
{
    (void)in_sizes; (void)n_in; (void)out_size;
    const float* X     = (const float*)d_in[0];
    const float* Wq    = (const float*)d_in[1];
    const float* Wk    = (const float*)d_in[2];
    const float* Wv    = (const float*)d_in[3];
    const float* gamma = (const float*)d_in[4];
    const float* beta  = (const float*)d_in[5];
    float* out = (float*)d_out;

    cudaFuncSetAttribute(k1_kv_mma, cudaFuncAttributeMaxDynamicSharedMemorySize,
                         K1_SMEM);    // 226 KB
    cudaFuncSetAttribute(k3_out_mma, cudaFuncAttributeMaxDynamicSharedMemorySize,
                         K3_SMEM);    // 192 KB

    k1_kv_mma<<<NPART, 512, K1_SMEM>>>(X, Wk, Wv, gamma, beta);
    k2a_reduce<<<64, 256>>>();
    k2b_fold<<<256, 256>>>(Wq);
    k3_out_mma<<<NPART, 512, K3_SMEM>>>(X, out);
}